// round 16
// baseline (speedup 1.0000x reference)
#include <cuda_runtime.h>
#include <cuda_fp16.h>
#include <math.h>
#include <stdint.h>

#define NROWS 32768
#define DIN   960
#define DH    1920
#define HALF_ROWS (NROWS / 2)

// ---------------- static device buffers (no allocations) ----------------
__device__ __half g_xph[(size_t)NROWS * DIN];
__device__ __half g_xpl[(size_t)NROWS * DIN];
__device__ float  g_h1 [(size_t)NROWS * DH];
__device__ __half g_h1h[(size_t)NROWS * DH];
__device__ __half g_h1l[(size_t)NROWS * DH];
__device__ float  g_h2 [(size_t)NROWS * DH];
__device__ __half g_h2h[(size_t)NROWS * DH];
__device__ __half g_h2l[(size_t)NROWS * DH];
__device__ float  g_outp[(size_t)NROWS * DIN];
__device__ float  g_sum0[256];
__device__ float  g_ssq[448];
__device__ __half g_wt1h[172032], g_wt1l[172032];
__device__ __half g_wt2h[344064], g_wt2l[344064];
__device__ __half g_wt3h[172032], g_wt3l[172032];
__device__ __half g_wtbh[86016],  g_wtbl[86016];

// ---------------- helpers ----------------
__device__ __forceinline__ uint32_t s2u(const void* p) {
    uint32_t a;
    asm("{ .reg .u64 t; cvta.to.shared.u64 t, %1; cvt.u32.u64 %0, t; }"
        : "=r"(a) : "l"(p));
    return a;
}

__device__ __forceinline__ void cp16(uint32_t dst, const void* src) {
    asm volatile("cp.async.cg.shared.global [%0], [%1], 16;"
                 :: "r"(dst), "l"(src));
}

__device__ __forceinline__ void ldmx4(uint32_t* r, uint32_t addr) {
    asm volatile("ldmatrix.sync.aligned.m8n8.x4.shared.b16 {%0,%1,%2,%3}, [%4];"
                 : "=r"(r[0]), "=r"(r[1]), "=r"(r[2]), "=r"(r[3]) : "r"(addr));
}

__device__ __forceinline__ void mma_f16(float* d, const uint32_t* a,
                                        uint32_t b0, uint32_t b1) {
    asm volatile(
        "mma.sync.aligned.m16n8k16.row.col.f32.f16.f16.f32 "
        "{%0,%1,%2,%3}, {%4,%5,%6,%7}, {%8,%9}, {%0,%1,%2,%3};"
        : "+f"(d[0]), "+f"(d[1]), "+f"(d[2]), "+f"(d[3])
        : "r"(a[0]), "r"(a[1]), "r"(a[2]), "r"(a[3]), "r"(b0), "r"(b1));
}

// ---------------- 3xFP16 GEMM (hi/lo split; hh+hl+lh), two operand sets ----
template <int BN>
__global__ __launch_bounds__(256, 2) void gemm_f16(
    const __half* __restrict__ A1h, const __half* __restrict__ A1l, int lda1, size_t sAz1,
    const __half* __restrict__ B1h, const __half* __restrict__ B1l, int ldb1, int nc1,
    const __half* __restrict__ A2h, const __half* __restrict__ A2l, int lda2, size_t sAz2,
    const __half* __restrict__ B2h, const __half* __restrict__ B2l, int ldb2, int nc2,
    float* __restrict__ C, __half* __restrict__ Ch, __half* __restrict__ Cl,
    int ldc, size_t sCz, int act)
{
    constexpr int WN = (BN == 128) ? 4 : 2;
    constexpr int MT = (BN == 128) ? 4 : 2;
    constexpr int ST = 3;
    constexpr int ASTG = 128 * 128;
    constexpr int BSTG = BN * 128;
    extern __shared__ char dsm[];
    char* sAb = dsm;
    char* sBb = dsm + ST * ASTG;

    A1h += (size_t)blockIdx.z * sAz1;  A1l += (size_t)blockIdx.z * sAz1;
    A2h += (size_t)blockIdx.z * sAz2;  A2l += (size_t)blockIdx.z * sAz2;
    C   += (size_t)blockIdx.z * sCz;
    Ch  += (size_t)blockIdx.z * sCz;
    Cl  += (size_t)blockIdx.z * sCz;

    const int tid = threadIdx.x, wid = tid >> 5, lane = tid & 31;
    const int g = lane >> 2, tig = lane & 3;
    const int wm = wid / WN, wn = wid % WN;
    const int row0 = blockIdx.y << 7;
    const int n0   = blockIdx.x * BN;
    const int tot  = nc1 + nc2;

    float acc[MT][4][4] = {};

    auto issue = [&](int cc, int s) {
        if (cc < tot) {
            const __half *Ah, *Al, *Bh, *Bl; int la, lb;
            if (cc < nc1) {
                Ah = A1h + (size_t)row0 * lda1 + cc * 32;
                Al = A1l + (size_t)row0 * lda1 + cc * 32;
                Bh = B1h + (size_t)n0 * ldb1 + cc * 32;
                Bl = B1l + (size_t)n0 * ldb1 + cc * 32;
                la = lda1; lb = ldb1;
            } else {
                int c2 = cc - nc1;
                Ah = A2h + (size_t)row0 * lda2 + c2 * 32;
                Al = A2l + (size_t)row0 * lda2 + c2 * 32;
                Bh = B2h + (size_t)n0 * ldb2 + c2 * 32;
                Bl = B2l + (size_t)n0 * ldb2 + c2 * 32;
                la = lda2; lb = ldb2;
            }
            uint32_t da = s2u(sAb + s * ASTG);
            #pragma unroll
            for (int i = tid; i < 1024; i += 256) {
                int r = i >> 3, u = i & 7;
                const __half* src = ((u & 4) ? Al : Ah) + (size_t)r * la + (u & 3) * 8;
                cp16(da + r * 128 + ((u ^ (r & 7)) << 4), src);
            }
            uint32_t db = s2u(sBb + s * BSTG);
            #pragma unroll
            for (int i = tid; i < BN * 8; i += 256) {
                int r = i >> 3, u = i & 7;
                const __half* src = ((u & 4) ? Bl : Bh) + (size_t)r * lb + (u & 3) * 8;
                cp16(db + r * 128 + ((u ^ (r & 7)) << 4), src);
            }
        }
        asm volatile("cp.async.commit_group;");
    };

    issue(0, 0); issue(1, 1); issue(2, 2);

    for (int cc = 0; cc < tot; cc++) {
        asm volatile("cp.async.wait_group 2;");
        __syncthreads();

        const int s = cc % ST;
        uint32_t aBase = s2u(sAb + s * ASTG);
        uint32_t bBase = s2u(sBb + s * BSTG);

        #pragma unroll
        for (int ks = 0; ks < 2; ks++) {
            uint32_t bh[2][4], bl[2][4];
            #pragma unroll
            for (int ntp = 0; ntp < 2; ntp++) {
                int brow = wn * 32 + ntp * 16 + (lane & 7) + ((lane & 16) >> 1);
                int u = ks * 2 + ((lane & 8) >> 3);
                ldmx4(bh[ntp], bBase + brow * 128 + (((u)     ^ (brow & 7)) << 4));
                ldmx4(bl[ntp], bBase + brow * 128 + (((u + 4) ^ (brow & 7)) << 4));
            }
            #pragma unroll
            for (int mp = 0; mp < MT / 2; mp++) {
                uint32_t ah[2][4], al[2][4];
                #pragma unroll
                for (int q = 0; q < 2; q++) {
                    int arow = wm * (MT * 16) + (mp * 2 + q) * 16 + (lane & 15);
                    int u = ks * 2 + ((lane & 16) >> 4);
                    ldmx4(ah[q], aBase + arow * 128 + (((u)     ^ (arow & 7)) << 4));
                    ldmx4(al[q], aBase + arow * 128 + (((u + 4) ^ (arow & 7)) << 4));
                }
                #pragma unroll
                for (int q = 0; q < 2; q++)
                    #pragma unroll
                    for (int nt = 0; nt < 4; nt++)
                        mma_f16(acc[mp * 2 + q][nt], ah[q],
                                bh[nt >> 1][(nt & 1) * 2], bh[nt >> 1][(nt & 1) * 2 + 1]);
                #pragma unroll
                for (int q = 0; q < 2; q++)
                    #pragma unroll
                    for (int nt = 0; nt < 4; nt++)
                        mma_f16(acc[mp * 2 + q][nt], ah[q],
                                bl[nt >> 1][(nt & 1) * 2], bl[nt >> 1][(nt & 1) * 2 + 1]);
                #pragma unroll
                for (int q = 0; q < 2; q++)
                    #pragma unroll
                    for (int nt = 0; nt < 4; nt++)
                        mma_f16(acc[mp * 2 + q][nt], al[q],
                                bh[nt >> 1][(nt & 1) * 2], bh[nt >> 1][(nt & 1) * 2 + 1]);
            }
        }
        __syncthreads();
        issue(cc + 3, s);
    }

    // epilogue
    #pragma unroll
    for (int mt = 0; mt < MT; mt++) {
        int r = row0 + wm * (MT * 16) + mt * 16 + g;
        #pragma unroll
        for (int nt = 0; nt < 4; nt++) {
            int cI = n0 + wn * 32 + nt * 8 + tig * 2;
            float v[4] = {acc[mt][nt][0], acc[mt][nt][1],
                          acc[mt][nt][2], acc[mt][nt][3]};
            size_t o0 = (size_t)r * ldc + cI;
            size_t o1 = o0 + (size_t)8 * ldc;
            if (act) {
                __half hh[4], hl[4];
                #pragma unroll
                for (int q = 0; q < 4; q++) {
                    float nn = sqrtf(v[q] * v[q] + 1e-8f);
                    float sg = 1.0f / (1.0f + expf(-nn));
                    float rr = v[q] * sg / nn;
                    hh[q] = __float2half_rn(rr);
                    hl[q] = __float2half_rn(rr - __half2float(hh[q]));
                }
                *(__half2*)(Ch + o0) = __halves2half2(hh[0], hh[1]);
                *(__half2*)(Ch + o1) = __halves2half2(hh[2], hh[3]);
                *(__half2*)(Cl + o0) = __halves2half2(hl[0], hl[1]);
                *(__half2*)(Cl + o1) = __halves2half2(hl[2], hl[3]);
            } else {
                *(float2*)(C + o0) = make_float2(v[0], v[1]);
                *(float2*)(C + o1) = make_float2(v[2], v[3]);
            }
        }
    }
}

// ---------------- fused weight prep ----------------
__global__ void conv_w_all(const float* __restrict__ w1, const float* __restrict__ w2,
                           const float* __restrict__ w3, const float* __restrict__ wb,
                           __half* __restrict__ t1h, __half* __restrict__ t1l,
                           __half* __restrict__ t2h, __half* __restrict__ t2l,
                           __half* __restrict__ t3h, __half* __restrict__ t3l,
                           __half* __restrict__ tbh, __half* __restrict__ tbl) {
    int idx = blockIdx.x * 256 + threadIdx.x;
    if (idx >= 774144) return;
    const int ends[12] = {131072, 163840, 172032, 434176, 499712, 516096,
                          647168, 679936, 688128, 753664, 770048, 774144};
    const int Ks[12]   = {256, 128, 64, 512, 256, 128, 512, 256, 128, 256, 128, 64};
    const int Ns[12]   = {512, 256, 128, 512, 256, 128, 256, 128, 64, 256, 128, 64};
    int sidx = 0;
    while (idx >= ends[sidx]) sidx++;
    int start = sidx ? ends[sidx - 1] : 0;
    const float* src; __half *dh, *dl; int tbase;
    if (sidx < 3)      { src = w1; dh = t1h; dl = t1l; tbase = 0; }
    else if (sidx < 6) { src = w2; dh = t2h; dl = t2l; tbase = 172032; }
    else if (sidx < 9) { src = w3; dh = t3h; dl = t3l; tbase = 516096; }
    else               { src = wb; dh = tbh; dl = tbl; tbase = 688128; }
    int segoff = start - tbase;
    int local  = idx - start;
    int K = Ks[sidx], Nout = Ns[sidx];
    int u = local / Nout, v = local - u * Nout;
    float val = src[segoff + local] * (1.0f / sqrtf((float)K));
    __half hi = __float2half_rn(val);
    size_t o = segoff + (size_t)v * K + u;
    dh[o] = hi;
    dl[o] = __float2half_rn(val - __half2float(hi));
}

// ---------------- x interleaved -> planar fp16 hi/lo ----------------
__global__ void to_planar_kernel(const float* __restrict__ x) {
    int idx = blockIdx.x * 256 + threadIdx.x;
    if (idx >= NROWS * DIN) return;
    int n = idx / DIN, j = idx - n * DIN;
    int src;
    if (j < 256) {
        src = j;
    } else if (j < 640) {
        int p = j - 256;
        src = 256 + (p & 127) * 3 + (p >> 7);
    } else {
        int p = j - 640;
        src = 640 + (p & 63) * 5 + (p >> 6);
    }
    float v = x[(size_t)n * DIN + src];
    __half hi = __float2half_rn(v);
    g_xph[idx] = hi;
    g_xpl[idx] = __float2half_rn(v - __half2float(hi));
}

// ---------------- NormActivation l>0 (row-range version) ----------------
template <int L>
__global__ void normact_kernel(const float* __restrict__ H,
                               __half* __restrict__ Hh, __half* __restrict__ Hl,
                               int o, int m, int nr) {
    int idx = blockIdx.x * 256 + threadIdx.x;
    if (idx >= nr * m) return;
    int n = idx / m, v = idx - n * m;
    const float* p = H + (size_t)n * DH + o + v;
    float f[L];
    float s2 = 1e-8f;
    #pragma unroll
    for (int i = 0; i < L; i++) { f[i] = p[(size_t)i * m]; s2 += f[i] * f[i]; }
    float nn = sqrtf(s2);
    float sg = 1.0f / (1.0f + expf(-nn));
    float sc = sg / nn;
    #pragma unroll
    for (int i = 0; i < L; i++) {
        float r = f[i] * sc;
        __half hi = __float2half_rn(r);
        size_t off = (size_t)n * DH + o + (size_t)i * m + v;
        Hh[off] = hi;
        Hl[off] = __float2half_rn(r - __half2float(hi));
    }
}

// ---------------- BatchNorm ----------------
__global__ void bn_zero_kernel() {
    int t = threadIdx.x;
    if (t < 256) g_sum0[t] = 0.0f;
    if (t < 448) g_ssq[t]  = 0.0f;
}

__global__ void bn_reduce_kernel() {
    const int tid = threadIdx.x;
    const int r0  = blockIdx.x * 128;
    float s[4] = {0, 0, 0, 0}, q[4] = {0, 0, 0, 0};
    for (int r = 0; r < 128; r++) {
        const float* row = g_outp + (size_t)(r0 + r) * DIN;
        #pragma unroll
        for (int k = 0; k < 4; k++) {
            int j = tid + (k << 8);
            if (j < DIN) {
                float v = row[j];
                s[k] += v;
                q[k] += v * v;
            }
        }
    }
    #pragma unroll
    for (int k = 0; k < 4; k++) {
        int j = tid + (k << 8);
        if (j >= DIN) continue;
        if (j < 256) {
            atomicAdd(&g_sum0[j], s[k]);
            atomicAdd(&g_ssq[j], q[k]);
        } else if (j < 640) {
            atomicAdd(&g_ssq[256 + ((j - 256) & 127)], q[k]);
        } else {
            atomicAdd(&g_ssq[384 + ((j - 640) & 63)], q[k]);
        }
    }
}

__global__ void bn_apply_kernel(const float* __restrict__ bnw,
                                const float* __restrict__ bnb,
                                float* __restrict__ out) {
    int idx = blockIdx.x * 256 + threadIdx.x;
    if (idx >= NROWS * DIN) return;
    int n = idx / DIN, jo = idx - n * DIN;
    const float invN = 1.0f / (float)NROWS;
    float g;
    if (jo < 256) {
        float f   = g_outp[(size_t)n * DIN + jo];
        float mu  = g_sum0[jo] * invN;
        float var = g_ssq[jo] * invN - mu * mu;
        g = (f - mu) * bnw[jo] * rsqrtf(var + 1e-5f) + bnb[jo];
    } else if (jo < 640) {
        int p = jo - 256, v = p / 3, i = p - v * 3;
        float f  = g_outp[(size_t)n * DIN + 256 + (i << 7) + v];
        float n2 = g_ssq[256 + v] * (invN * (1.0f / 3.0f));
        g = f * bnw[256 + v] * rsqrtf(n2 + 1e-5f);
    } else {
        int p = jo - 640, v = p / 5, i = p - v * 5;
        float f  = g_outp[(size_t)n * DIN + 640 + (i << 6) + v];
        float n2 = g_ssq[384 + v] * (invN * (1.0f / 5.0f));
        g = f * bnw[384 + v] * rsqrtf(n2 + 1e-5f);
    }
    out[idx] = g;
}

// ---------------- launch ----------------
#define SMEM128 (3 * (128 * 128 + 128 * 128))   // 98304
#define SMEM64  (3 * (128 * 128 + 64 * 128))    // 73728

extern "C" void kernel_launch(void* const* d_in, const int* in_sizes, int n_in,
                              void* d_out, int out_size) {
    const float* x   = (const float*)d_in[0];
    const float* w1  = (const float*)d_in[1];
    const float* w2  = (const float*)d_in[2];
    const float* w3  = (const float*)d_in[3];
    const float* wb  = (const float*)d_in[4];
    const float* bnw = (const float*)d_in[5];
    const float* bnb = (const float*)d_in[6];
    float* out = (float*)d_out;

    // EXACT same host-resource budget as the passing R14 config: 3 streams, 4 events.
    static int inited = 0;
    static cudaStream_t s1, s2, s3;
    static cudaEvent_t e0, eb1, eb2, eb3;
    if (!inited) {
        cudaFuncSetAttribute(gemm_f16<128>, cudaFuncAttributeMaxDynamicSharedMemorySize, SMEM128);
        cudaFuncSetAttribute(gemm_f16<64>,  cudaFuncAttributeMaxDynamicSharedMemorySize, SMEM64);
        cudaStreamCreateWithFlags(&s1, cudaStreamNonBlocking);
        cudaStreamCreateWithFlags(&s2, cudaStreamNonBlocking);
        cudaStreamCreateWithFlags(&s3, cudaStreamNonBlocking);
        cudaEventCreateWithFlags(&e0,  cudaEventDisableTiming);
        cudaEventCreateWithFlags(&eb1, cudaEventDisableTiming);
        cudaEventCreateWithFlags(&eb2, cudaEventDisableTiming);
        cudaEventCreateWithFlags(&eb3, cudaEventDisableTiming);
        inited = 1;
    }

    __half *xph, *xpl, *h1h, *h1l, *h2h, *h2l;
    __half *w1h, *w1l, *w2h, *w2l, *w3h, *w3l, *wbh, *wbl;
    float *h1, *h2, *op;
    cudaGetSymbolAddress((void**)&xph, g_xph);
    cudaGetSymbolAddress((void**)&xpl, g_xpl);
    cudaGetSymbolAddress((void**)&h1,  g_h1);
    cudaGetSymbolAddress((void**)&h1h, g_h1h);
    cudaGetSymbolAddress((void**)&h1l, g_h1l);
    cudaGetSymbolAddress((void**)&h2,  g_h2);
    cudaGetSymbolAddress((void**)&h2h, g_h2h);
    cudaGetSymbolAddress((void**)&h2l, g_h2l);
    cudaGetSymbolAddress((void**)&op,  g_outp);
    cudaGetSymbolAddress((void**)&w1h, g_wt1h);
    cudaGetSymbolAddress((void**)&w1l, g_wt1l);
    cudaGetSymbolAddress((void**)&w2h, g_wt2h);
    cudaGetSymbolAddress((void**)&w2l, g_wt2l);
    cudaGetSymbolAddress((void**)&w3h, g_wt3h);
    cudaGetSymbolAddress((void**)&w3l, g_wt3l);
    cudaGetSymbolAddress((void**)&wbh, g_wtbh);
    cudaGetSymbolAddress((void**)&wbl, g_wtbl);

    auto gemm = [&](cudaStream_t s, int rb,
                    const __half* Ah, const __half* Al, int lda, size_t sAz,
                    const __half* Bh, const __half* Bl,
                    float* Cf, __half* Chp, __half* Clp, int ldc, size_t sCz,
                    int K, int Nout, int nz, int act) {
        const __half* Ahr = Ah + (size_t)rb * lda;
        const __half* Alr = Al + (size_t)rb * lda;
        float*  Cfr = Cf  ? Cf  + (size_t)rb * ldc : 0;
        __half* Chr = Chp ? Chp + (size_t)rb * ldc : 0;
        __half* Clr = Clp ? Clp + (size_t)rb * ldc : 0;
        if (Nout >= 128) {
            dim3 grid(Nout / 128, HALF_ROWS / 128, nz);
            gemm_f16<128><<<grid, 256, SMEM128, s>>>(
                Ahr, Alr, lda, sAz, Bh, Bl, K, K / 32,
                Ahr, Alr, lda, sAz, Bh, Bl, K, 0,
                Cfr, Chr, Clr, ldc, sCz, act);
        } else {
            dim3 grid(Nout / 64, HALF_ROWS / 128, nz);
            gemm_f16<64><<<grid, 256, SMEM64, s>>>(
                Ahr, Alr, lda, sAz, Bh, Bl, K, K / 32,
                Ahr, Alr, lda, sAz, Bh, Bl, K, 0,
                Cfr, Chr, Clr, ldc, sCz, act);
        }
    };
    auto gemm2 = [&](cudaStream_t s, int rb,
                     const __half* A1hp, const __half* A1lp, int lda1, size_t sAz1,
                     const __half* B1hp, const __half* B1lp, int K1,
                     const __half* A2hp, const __half* A2lp, int lda2, size_t sAz2,
                     const __half* B2hp, const __half* B2lp, int K2,
                     float* Cf, int ldc, size_t sCz, int Nout, int nz) {
        const __half* A1hr = A1hp + (size_t)rb * lda1;
        const __half* A1lr = A1lp + (size_t)rb * lda1;
        const __half* A2hr = A2hp + (size_t)rb * lda2;
        const __half* A2lr = A2lp + (size_t)rb * lda2;
        float* Cfr = Cf + (size_t)rb * ldc;
        if (Nout >= 128) {
            dim3 grid(Nout / 128, HALF_ROWS / 128, nz);
            gemm_f16<128><<<grid, 256, SMEM128, s>>>(
                A1hr, A1lr, lda1, sAz1, B1hp, B1lp, K1, K1 / 32,
                A2hr, A2lr, lda2, sAz2, B2hp, B2lp, K2, K2 / 32,
                Cfr, (__half*)Cfr, (__half*)Cfr, ldc, sCz, 0);
        } else {
            dim3 grid(Nout / 64, HALF_ROWS / 128, nz);
            gemm_f16<64><<<grid, 256, SMEM64, s>>>(
                A1hr, A1lr, lda1, sAz1, B1hp, B1lp, K1, K1 / 32,
                A2hr, A2lr, lda2, sAz2, B2hp, B2lp, K2, K2 / 32,
                Cfr, (__half*)Cfr, (__half*)Cfr, ldc, sCz, 0);
        }
    };
    auto normact3 = [&](cudaStream_t s, int rb) {
        normact_kernel<3><<<(HALF_ROWS * 256) / 256, 256, 0, s>>>(
            (const float*)0, (__half*)0, (__half*)0, 0, 0, 0);  // placeholder (unused)
    };
    (void)normact3;

    auto na3 = [&](cudaStream_t s, int rb, const float* H, __half* Hh, __half* Hl) {
        normact_kernel<3><<<(HALF_ROWS * 256) / 256, 256, 0, s>>>(
            H + (size_t)rb * DH, Hh + (size_t)rb * DH, Hl + (size_t)rb * DH, 512, 256, HALF_ROWS);
    };
    auto na5 = [&](cudaStream_t s, int rb, const float* H, __half* Hh, __half* Hl) {
        normact_kernel<5><<<(HALF_ROWS * 128) / 256, 256, 0, s>>>(
            H + (size_t)rb * DH, Hh + (size_t)rb * DH, Hl + (size_t)rb * DH, 1280, 128, HALF_ROWS);
    };

    // chain builders
    auto chain_l0 = [&](cudaStream_t s, int rb) {
        gemm(s, rb, xph, xpl, DIN, 0, w1h, w1l, 0, h1h, h1l, DH, 0, 256, 512, 1, 1);
        gemm(s, rb, h1h, h1l, DH, 0, w2h, w2l, 0, h2h, h2l, DH, 0, 512, 512, 1, 1);
        gemm2(s, rb, h2h, h2l, DH, 0, w3h, w3l, 512,
              xph, xpl, DIN, 0, wbh, wbl, 256, op, DIN, 0, 256, 1);
    };
    auto chain_l1 = [&](cudaStream_t s, int rb) {
        gemm(s, rb, xph + 256, xpl + 256, DIN, 128, w1h + 131072, w1l + 131072,
             h1 + 512, 0, 0, DH, 256, 128, 256, 3, 0);
        na3(s, rb, h1, h1h, h1l);
        gemm(s, rb, h1h + 512, h1l + 512, DH, 256, w2h + 262144, w2l + 262144,
             h2 + 512, 0, 0, DH, 256, 256, 256, 3, 0);
        na3(s, rb, h2, h2h, h2l);
        gemm2(s, rb, h2h + 512, h2l + 512, DH, 256, w3h + 131072, w3l + 131072, 256,
              xph + 256, xpl + 256, DIN, 128, wbh + 65536, wbl + 65536, 128,
              op + 256, DIN, 128, 128, 3);
    };
    auto chain_l2 = [&](cudaStream_t s, int rb) {
        gemm(s, rb, xph + 640, xpl + 640, DIN, 64, w1h + 163840, w1l + 163840,
             h1 + 1280, 0, 0, DH, 128, 64, 128, 5, 0);
        na5(s, rb, h1, h1h, h1l);
        gemm(s, rb, h1h + 1280, h1l + 1280, DH, 128, w2h + 327680, w2l + 327680,
             h2 + 1280, 0, 0, DH, 128, 128, 128, 5, 0);
        na5(s, rb, h2, h2h, h2l);
        gemm2(s, rb, h2h + 1280, h2l + 1280, DH, 128, w3h + 163840, w3l + 163840, 128,
              xph + 640, xpl + 640, DIN, 64, wbh + 81920, wbl + 81920, 64,
              op + 640, DIN, 64, 64, 5);
    };

    // ---- prologue on the capture stream ----
    conv_w_all<<<3024, 256>>>(w1, w2, w3, wb, w1h, w1l, w2h, w2l, w3h, w3l, wbh, wbl);
    to_planar_kernel<<<(NROWS * DIN) / 256, 256>>>(x);
    bn_zero_kernel<<<1, 512>>>();
    cudaEventRecord(e0, 0);
    cudaStreamWaitEvent(s1, e0, 0);
    cudaStreamWaitEvent(s2, e0, 0);
    cudaStreamWaitEvent(s3, e0, 0);

    // 4 lanes, 6 half-row chains, balanced:
    //   default: l0(h0)           (~294)
    //   s1:      l0(h1)           (~294)
    //   s2:      l1(h0) + l2(h0)  (~313)
    //   s3:      l1(h1) + l2(h1)  (~313)
    chain_l0(0,  0);
    chain_l0(s1, HALF_ROWS);
    chain_l1(s2, 0);
    chain_l2(s2, 0);
    chain_l1(s3, HALF_ROWS);
    chain_l2(s3, HALF_ROWS);
    cudaEventRecord(eb1, s1);
    cudaEventRecord(eb2, s2);
    cudaEventRecord(eb3, s3);

    // ---- join, then batch norm on the capture stream ----
    cudaStreamWaitEvent(0, eb1, 0);
    cudaStreamWaitEvent(0, eb2, 0);
    cudaStreamWaitEvent(0, eb3, 0);
    bn_reduce_kernel<<<256, 256>>>();
    bn_apply_kernel<<<(NROWS * DIN) / 256, 256>>>(bnw, bnb, out);
}